// round 15
// baseline (speedup 1.0000x reference)
#include <cuda_runtime.h>
#include <cuda_bf16.h>
#include <cstdint>
#include <math.h>

#define B_SZ   2
#define SEQ    4096
#define DMODEL 768
#define DPROJ  3352
#define DINNER 1536
#define DXBC   1792
#define NH     24
#define HD     64
#define DSTATE 128
#define CH     128
#define NC     32
#define MROWS  (B_SZ*SEQ)

// ---------------- scratch (static device arrays; no runtime alloc) ----------
__device__ float g_zxbcdt[(size_t)MROWS*DPROJ];
__device__ float g_x[(size_t)MROWS*DINNER];
__device__ float g_dt[(size_t)MROWS*NH];
__device__ float g_Bm[(size_t)MROWS*DSTATE];
__device__ float g_Cm[(size_t)MROWS*DSTATE];
__device__ float g_CB[(size_t)B_SZ*NC*CH*CH];
__device__ float g_Acum[(size_t)B_SZ*NC*NH*CH];
__device__ float g_Alast[(size_t)B_SZ*NC*NH];
__device__ float g_states[(size_t)B_SZ*NC*NH*HD*DSTATE];
__device__ float g_y[(size_t)MROWS*DINNER];

// =================== tf32 / async helpers ====================================
__device__ __forceinline__ unsigned f2tf(float x) {
    unsigned r;
    asm("cvt.rna.tf32.f32 %0, %1;" : "=r"(r) : "f"(x));
    return r;
}

__device__ __forceinline__ void mma_tf32(float* d, const unsigned* a, const unsigned* b) {
    asm volatile(
        "mma.sync.aligned.m16n8k8.row.col.f32.tf32.tf32.f32 "
        "{%0,%1,%2,%3}, {%4,%5,%6,%7}, {%8,%9}, {%0,%1,%2,%3};"
        : "+f"(d[0]), "+f"(d[1]), "+f"(d[2]), "+f"(d[3])
        : "r"(a[0]), "r"(a[1]), "r"(a[2]), "r"(a[3]), "r"(b[0]), "r"(b[1]));
}

__device__ __forceinline__ void cp16(void* smem, const void* gmem) {
    unsigned sa = (unsigned)__cvta_generic_to_shared(smem);
    asm volatile("cp.async.ca.shared.global [%0], [%1], 16;" :: "r"(sa), "l"(gmem));
}

// ============ tf32 tensor-core NT GEMM: out = X(MxK) * W(NxK)^T =============
// 128x128 block tile, BK=16, 2-stage cp.async pipeline, 8 warps (4x2), 2 CTAs/SM.
__global__ __launch_bounds__(256, 2)
void gemm_tf32(const float* __restrict__ X, const float* __restrict__ W,
               float* __restrict__ out, int M, int N, int K,
               const float* __restrict__ resid, const float* __restrict__ gate)
{
    __shared__ float As[2][128][20];
    __shared__ float Bs[2][128][20];

    const int tid  = threadIdx.x;
    const int warp = tid >> 5;
    const int lane = tid & 31;
    const int gid  = lane >> 2;
    const int tig  = lane & 3;
    const int wm   = warp >> 1;
    const int wn   = warp & 1;

    const int m0 = blockIdx.y * 128;
    const int n0 = blockIdx.x * 128;

    const int lr = tid >> 2;
    const int lc = (tid & 3) * 4;

    const bool bv0 = (n0 + lr      < N);
    const bool bv1 = (n0 + lr + 64 < N);

    if (!bv0) { *(float4*)&Bs[0][lr][lc] = make_float4(0,0,0,0);
                *(float4*)&Bs[1][lr][lc] = make_float4(0,0,0,0); }
    if (!bv1) { *(float4*)&Bs[0][lr+64][lc] = make_float4(0,0,0,0);
                *(float4*)&Bs[1][lr+64][lc] = make_float4(0,0,0,0); }

    float acc[2][8][4];
    #pragma unroll
    for (int i = 0; i < 2; i++)
        #pragma unroll
        for (int j = 0; j < 8; j++)
            #pragma unroll
            for (int c = 0; c < 4; c++) acc[i][j][c] = 0.f;

    const int ktiles = K >> 4;

    const float* gA0 = X + (size_t)(m0 + lr) * K + lc;
    const float* gA1 = X + (size_t)(m0 + lr + 64) * K + lc;
    const float* gB0 = W + (size_t)(n0 + lr) * K + lc;
    const float* gB1 = W + (size_t)(n0 + lr + 64) * K + lc;

    cp16(&As[0][lr][lc],      gA0);
    cp16(&As[0][lr + 64][lc], gA1);
    if (bv0) cp16(&Bs[0][lr][lc],      gB0);
    if (bv1) cp16(&Bs[0][lr + 64][lc], gB1);
    asm volatile("cp.async.commit_group;");

    for (int kt = 0; kt < ktiles; kt++) {
        const int s = kt & 1;
        if (kt + 1 < ktiles) {
            const int ko = (kt + 1) * 16;
            cp16(&As[s ^ 1][lr][lc],      gA0 + ko);
            cp16(&As[s ^ 1][lr + 64][lc], gA1 + ko);
            if (bv0) cp16(&Bs[s ^ 1][lr][lc],      gB0 + ko);
            if (bv1) cp16(&Bs[s ^ 1][lr + 64][lc], gB1 + ko);
            asm volatile("cp.async.commit_group;");
            asm volatile("cp.async.wait_group 1;");
        } else {
            asm volatile("cp.async.wait_group 0;");
        }
        __syncthreads();

        #pragma unroll
        for (int kk = 0; kk < 16; kk += 8) {
            unsigned afr[2][4];
            #pragma unroll
            for (int mi = 0; mi < 2; mi++) {
                const int rm = wm * 32 + mi * 16;
                afr[mi][0] = f2tf(As[s][rm + gid    ][kk + tig]);
                afr[mi][1] = f2tf(As[s][rm + gid + 8][kk + tig]);
                afr[mi][2] = f2tf(As[s][rm + gid    ][kk + tig + 4]);
                afr[mi][3] = f2tf(As[s][rm + gid + 8][kk + tig + 4]);
            }
            #pragma unroll
            for (int j = 0; j < 8; j++) {
                const int nn = wn * 64 + j * 8 + gid;
                unsigned bfr[2];
                bfr[0] = f2tf(Bs[s][nn][kk + tig]);
                bfr[1] = f2tf(Bs[s][nn][kk + tig + 4]);
                mma_tf32(acc[0][j], afr[0], bfr);
                mma_tf32(acc[1][j], afr[1], bfr);
            }
        }
        __syncthreads();
    }

    float sg = 1.f;
    if (gate) sg = 1.f / (1.f + expf(-gate[0]));

    #pragma unroll
    for (int mi = 0; mi < 2; mi++) {
        #pragma unroll
        for (int j = 0; j < 8; j++) {
            const int n = n0 + wn * 64 + j * 8 + tig * 2;
            #pragma unroll
            for (int rr = 0; rr < 2; rr++) {
                const int m = m0 + wm * 32 + mi * 16 + gid + rr * 8;
                float v0 = acc[mi][j][rr * 2 + 0];
                float v1 = acc[mi][j][rr * 2 + 1];
                if (resid) {
                    if (n     < N) out[(size_t)m * N + n]     = sg * v0 + resid[(size_t)m * N + n];
                    if (n + 1 < N) out[(size_t)m * N + n + 1] = sg * v1 + resid[(size_t)m * N + n + 1];
                } else {
                    if (n     < N) out[(size_t)m * N + n]     = v0;
                    if (n + 1 < N) out[(size_t)m * N + n + 1] = v1;
                }
            }
        }
    }
}

// ====================== conv1d + SiLU (float4 over channels) ================
__global__ void conv_act(const float* __restrict__ conv_w,
                         const float* __restrict__ conv_b)
{
    int idx = blockIdx.x * blockDim.x + threadIdx.x;
    const int J4 = DXBC / 4;
    if (idx >= B_SZ * SEQ * J4) return;
    int j4 = idx % J4;
    int l  = (idx / J4) % SEQ;
    int b  = idx / (J4 * SEQ);
    int j  = j4 * 4;

    const float* base = g_zxbcdt + (size_t)b * SEQ * DPROJ + DINNER + j;
    float4 acc = make_float4(conv_b[j], conv_b[j+1], conv_b[j+2], conv_b[j+3]);
    #pragma unroll
    for (int k = 0; k < 4; k++) {
        int li = l + k - 3;
        if (li >= 0) {
            float4 v = *(const float4*)(base + (size_t)li * DPROJ);
            acc.x = fmaf(conv_w[(j+0)*4 + k], v.x, acc.x);
            acc.y = fmaf(conv_w[(j+1)*4 + k], v.y, acc.y);
            acc.z = fmaf(conv_w[(j+2)*4 + k], v.z, acc.z);
            acc.w = fmaf(conv_w[(j+3)*4 + k], v.w, acc.w);
        }
    }
    float4 v4;
    v4.x = acc.x / (1.f + expf(-acc.x));
    v4.y = acc.y / (1.f + expf(-acc.y));
    v4.z = acc.z / (1.f + expf(-acc.z));
    v4.w = acc.w / (1.f + expf(-acc.w));

    size_t row = (size_t)b * SEQ + l;
    if (j < DINNER)               *(float4*)&g_x [row * DINNER + j] = v4;
    else if (j < DINNER + DSTATE) *(float4*)&g_Bm[row * DSTATE + (j - DINNER)] = v4;
    else                          *(float4*)&g_Cm[row * DSTATE + (j - DINNER - DSTATE)] = v4;
}

// ============================ dt = softplus ==================================
__global__ void dt_kernel(const float* __restrict__ dt_bias)
{
    int idx = blockIdx.x * blockDim.x + threadIdx.x;
    if (idx >= MROWS * NH) return;
    int h = idx % NH;
    size_t row = idx / NH;
    float x = g_zxbcdt[row * DPROJ + (DPROJ - NH) + h] + dt_bias[h];
    g_dt[idx] = (x > 20.f) ? x : log1pf(expf(x));
}

// ========== CB[l][s] = sum_n C[l,n]*B[s,n], split 4-way over l ==============
__global__ __launch_bounds__(512)
void cb_kernel()
{
    int c = blockIdx.x, b = blockIdx.y, z = blockIdx.z;
    extern __shared__ float sm[];
    float* Csh = sm;               // 32*132
    float* Bsh = sm + 32 * 132;    // 128*132
    int tid = threadIdx.x;
    size_t rowbase = (size_t)b * SEQ + (size_t)c * CH;
    const int l0 = z * 32;

    for (int t = tid; t < 32 * 128; t += 512) {
        int l = t >> 7, n = t & 127;
        Csh[l * 132 + n] = g_Cm[(rowbase + l0 + l) * DSTATE + n];
    }
    for (int t = tid; t < 128 * 128; t += 512) {
        int s = t >> 7, n = t & 127;
        Bsh[s * 132 + n] = g_Bm[(rowbase + s) * DSTATE + n];
    }
    __syncthreads();

    int ty = tid >> 5, tx = tid & 31;
    float acc[2][4];
    #pragma unroll
    for (int i = 0; i < 2; i++)
        #pragma unroll
        for (int j = 0; j < 4; j++) acc[i][j] = 0.f;

    for (int n = 0; n < 128; n += 4) {
        float4 cv[2], bvv[4];
        #pragma unroll
        for (int i = 0; i < 2; i++) cv[i] = *(const float4*)&Csh[(ty * 2 + i) * 132 + n];
        #pragma unroll
        for (int j = 0; j < 4; j++) bvv[j] = *(const float4*)&Bsh[(tx * 4 + j) * 132 + n];
        #pragma unroll
        for (int i = 0; i < 2; i++)
            #pragma unroll
            for (int j = 0; j < 4; j++)
                acc[i][j] += cv[i].x * bvv[j].x + cv[i].y * bvv[j].y
                           + cv[i].z * bvv[j].z + cv[i].w * bvv[j].w;
    }

    float* outp = g_CB + ((size_t)b * NC + c) * CH * CH;
    #pragma unroll
    for (int i = 0; i < 2; i++)
        #pragma unroll
        for (int j = 0; j < 4; j++)
            outp[(l0 + ty * 2 + i) * CH + tx * 4 + j] = acc[i][j];
}

// ========== per (b,c,h): cumsum, Y_diag (MMA), states (MMA) ==================
__global__ __launch_bounds__(256)
void chunk_kernel(const float* __restrict__ A_log)
{
    int c = blockIdx.x, h = blockIdx.y, b = blockIdx.z;
    extern __shared__ float sm[];
    float* Ac   = sm;                    // 128
    float* wd   = sm + 128;              // 128
    float* G    = sm + 256;              // 128*132   [l][s]
    float* xdsT = G + 128 * 132;         // 64*132    [p][l]
    float* BsT  = xdsT + 64 * 132;       // 128*132   [n][l]

    const int tid  = threadIdx.x;
    const int warp = tid >> 5;
    const int lane = tid & 31;
    const int gid  = lane >> 2;
    const int tig  = lane & 3;
    size_t rowbase = (size_t)b * SEQ + (size_t)c * CH;

    // ---- chunk-local inclusive cumsum of dt*A ----
    if (tid < 128) {
        float Ah  = -expf(A_log[h]);
        float dtv = g_dt[(rowbase + tid) * NH + h];
        Ac[tid] = dtv * Ah;
    }
    __syncthreads();
    for (int off = 1; off < 128; off <<= 1) {
        float add = 0.f;
        if (tid < 128 && tid >= off) add = Ac[tid - off];
        __syncthreads();
        if (tid < 128) Ac[tid] += add;
        __syncthreads();
    }
    float Alast = Ac[127];
    if (tid < 128) {
        wd[tid] = expf(Alast - Ac[tid]);
        g_Acum[(((size_t)b * NC + c) * NH + h) * CH + tid] = Ac[tid];
    }
    if (tid == 127) g_Alast[((size_t)b * NC + c) * NH + h] = Alast;

    // ---- stage xd^T [p][l], B^T [n][l], masked decay matrix G [l][s] ----
    for (int t = tid; t < 128 * 64; t += 256) {
        int l = t >> 6, p = t & 63;
        size_t row = rowbase + l;
        xdsT[p * 132 + l] = g_x[row * DINNER + h * HD + p] * g_dt[row * NH + h];
    }
    for (int t = tid; t < 128 * 128; t += 256) {
        int l = t >> 7, n = t & 127;
        BsT[n * 132 + l] = g_Bm[(rowbase + l) * DSTATE + n];
    }
    const float* CBp = g_CB + ((size_t)b * NC + c) * CH * CH;
    for (int t = tid; t < 128 * 128; t += 256) {
        int l = t >> 7, s = t & 127;
        G[l * 132 + s] = (s <= l) ? CBp[t] * expf(Ac[l] - Ac[s]) : 0.f;
    }
    __syncthreads();

    // ---- Y_diag[l,p] = sum_s G[l,s] * xd[s,p] via MMA (M=128,N=64,K=128) ----
    {
        const int wm = warp >> 1;   // 0..3
        const int wn = warp & 1;    // 0..1
        float acc[2][4][4];
        #pragma unroll
        for (int i = 0; i < 2; i++)
            #pragma unroll
            for (int j = 0; j < 4; j++)
                #pragma unroll
                for (int k = 0; k < 4; k++) acc[i][j][k] = 0.f;

        for (int kk = 0; kk < 128; kk += 8) {
            unsigned afr[2][4];
            #pragma unroll
            for (int mi = 0; mi < 2; mi++) {
                const int rm = wm * 32 + mi * 16;
                afr[mi][0] = f2tf(G[(rm + gid    ) * 132 + kk + tig]);
                afr[mi][1] = f2tf(G[(rm + gid + 8) * 132 + kk + tig]);
                afr[mi][2] = f2tf(G[(rm + gid    ) * 132 + kk + tig + 4]);
                afr[mi][3] = f2tf(G[(rm + gid + 8) * 132 + kk + tig + 4]);
            }
            #pragma unroll
            for (int nj = 0; nj < 4; nj++) {
                const int nn = wn * 32 + nj * 8 + gid;
                unsigned bfr[2];
                bfr[0] = f2tf(xdsT[nn * 132 + kk + tig]);
                bfr[1] = f2tf(xdsT[nn * 132 + kk + tig + 4]);
                mma_tf32(acc[0][nj], afr[0], bfr);
                mma_tf32(acc[1][nj], afr[1], bfr);
            }
        }
        #pragma unroll
        for (int mi = 0; mi < 2; mi++) {
            #pragma unroll
            for (int nj = 0; nj < 4; nj++) {
                const int n = wn * 32 + nj * 8 + tig * 2;
                #pragma unroll
                for (int rr = 0; rr < 2; rr++) {
                    const int m = wm * 32 + mi * 16 + gid + rr * 8;
                    size_t idx = (rowbase + m) * DINNER + h * HD + n;
                    g_y[idx]     = acc[mi][nj][rr * 2 + 0];
                    g_y[idx + 1] = acc[mi][nj][rr * 2 + 1];
                }
            }
        }
    }

    // ---- states[p,n] = sum_l xd[l,p]*wd[l]*B[l,n] via MMA (M=64,N=128,K=128) ----
    {
        const int wm = warp >> 2;   // 0..1
        const int wn = warp & 3;    // 0..3
        float acc[2][4][4];
        #pragma unroll
        for (int i = 0; i < 2; i++)
            #pragma unroll
            for (int j = 0; j < 4; j++)
                #pragma unroll
                for (int k = 0; k < 4; k++) acc[i][j][k] = 0.f;

        for (int kk = 0; kk < 128; kk += 8) {
            const float wlo = wd[kk + tig];
            const float whi = wd[kk + tig + 4];
            unsigned afr[2][4];
            #pragma unroll
            for (int mi = 0; mi < 2; mi++) {
                const int rm = wm * 32 + mi * 16;
                afr[mi][0] = f2tf(xdsT[(rm + gid    ) * 132 + kk + tig] * wlo);
                afr[mi][1] = f2tf(xdsT[(rm + gid + 8) * 132 + kk + tig] * wlo);
                afr[mi][2] = f2tf(xdsT[(rm + gid    ) * 132 + kk + tig + 4] * whi);
                afr[mi][3] = f2tf(xdsT[(rm + gid + 8) * 132 + kk + tig + 4] * whi);
            }
            #pragma unroll
            for (int nj = 0; nj < 4; nj++) {
                const int nn = wn * 32 + nj * 8 + gid;
                unsigned bfr[2];
                bfr[0] = f2tf(BsT[nn * 132 + kk + tig]);
                bfr[1] = f2tf(BsT[nn * 132 + kk + tig + 4]);
                mma_tf32(acc[0][nj], afr[0], bfr);
                mma_tf32(acc[1][nj], afr[1], bfr);
            }
        }
        float* sp = g_states + (((size_t)b * NC + c) * NH + h) * HD * DSTATE;
        #pragma unroll
        for (int mi = 0; mi < 2; mi++) {
            #pragma unroll
            for (int nj = 0; nj < 4; nj++) {
                const int n = wn * 32 + nj * 8 + tig * 2;
                #pragma unroll
                for (int rr = 0; rr < 2; rr++) {
                    const int m = wm * 32 + mi * 16 + gid + rr * 8;
                    sp[(size_t)m * DSTATE + n]     = acc[mi][nj][rr * 2 + 0];
                    sp[(size_t)m * DSTATE + n + 1] = acc[mi][nj][rr * 2 + 1];
                }
            }
        }
    }
}

// ========== inter-chunk scan (full-chip: 8 segments per (b,h)) ==============
__global__ __launch_bounds__(256)
void scan_kernel()
{
    int blk = blockIdx.x;
    int seg = blk & 7;
    int bh  = blk >> 3;
    int b = bh / NH, h = bh % NH;
    int t4 = seg * 256 + threadIdx.x;

    float4 run = make_float4(0.f, 0.f, 0.f, 0.f);
    for (int c = 0; c < NC; c++) {
        float el = expf(g_Alast[((size_t)b * NC + c) * NH + h]);
        float4* sp = (float4*)(g_states + (((size_t)b * NC + c) * NH + h) * (HD * DSTATE)) + t4;
        float4 s = *sp;
        *sp = run;
        run.x = fmaf(run.x, el, s.x);
        run.y = fmaf(run.y, el, s.y);
        run.z = fmaf(run.z, el, s.z);
        run.w = fmaf(run.w, el, s.w);
    }
}

// ==== Y_off[l,p] = e^{Acum[l]} * sum_n C[l,n]*prev[p,n] via MMA; + D*x ======
__global__ __launch_bounds__(256)
void yoff_kernel(const float* __restrict__ Dp)
{
    int c = blockIdx.x, h = blockIdx.y, b = blockIdx.z;
    extern __shared__ float sm[];
    float* Csh = sm;               // 128*132  [l][n]
    float* Pv  = sm + 128 * 132;   // 64*132   [p][n]
    const int tid  = threadIdx.x;
    const int warp = tid >> 5;
    const int lane = tid & 31;
    const int gid  = lane >> 2;
    const int tig  = lane & 3;
    size_t rowbase = (size_t)b * SEQ + (size_t)c * CH;

    for (int t = tid; t < 128 * 128; t += 256) {
        int l = t >> 7, n = t & 127;
        Csh[l * 132 + n] = g_Cm[(rowbase + l) * DSTATE + n];
    }
    const float* sp = g_states + (((size_t)b * NC + c) * NH + h) * HD * DSTATE;
    for (int t = tid; t < 64 * 128; t += 256) {
        int p = t >> 7, n = t & 127;
        Pv[p * 132 + n] = sp[t];
    }
    __syncthreads();

    const int wm = warp >> 1;   // 0..3
    const int wn = warp & 1;    // 0..1
    float acc[2][4][4];
    #pragma unroll
    for (int i = 0; i < 2; i++)
        #pragma unroll
        for (int j = 0; j < 4; j++)
            #pragma unroll
            for (int k = 0; k < 4; k++) acc[i][j][k] = 0.f;

    for (int kk = 0; kk < 128; kk += 8) {
        unsigned afr[2][4];
        #pragma unroll
        for (int mi = 0; mi < 2; mi++) {
            const int rm = wm * 32 + mi * 16;
            afr[mi][0] = f2tf(Csh[(rm + gid    ) * 132 + kk + tig]);
            afr[mi][1] = f2tf(Csh[(rm + gid + 8) * 132 + kk + tig]);
            afr[mi][2] = f2tf(Csh[(rm + gid    ) * 132 + kk + tig + 4]);
            afr[mi][3] = f2tf(Csh[(rm + gid + 8) * 132 + kk + tig + 4]);
        }
        #pragma unroll
        for (int nj = 0; nj < 4; nj++) {
            const int nn = wn * 32 + nj * 8 + gid;
            unsigned bfr[2];
            bfr[0] = f2tf(Pv[nn * 132 + kk + tig]);
            bfr[1] = f2tf(Pv[nn * 132 + kk + tig + 4]);
            mma_tf32(acc[0][nj], afr[0], bfr);
            mma_tf32(acc[1][nj], afr[1], bfr);
        }
    }

    const float dh = Dp[h];
    const float* acp = g_Acum + (((size_t)b * NC + c) * NH + h) * CH;
    #pragma unroll
    for (int mi = 0; mi < 2; mi++) {
        #pragma unroll
        for (int rr = 0; rr < 2; rr++) {
            const int l = wm * 32 + mi * 16 + gid + rr * 8;
            const float el = expf(acp[l]);
            #pragma unroll
            for (int nj = 0; nj < 4; nj++) {
                const int n = wn * 32 + nj * 8 + tig * 2;
                size_t idx = (rowbase + l) * DINNER + h * HD + n;
                g_y[idx]     += el * acc[mi][nj][rr * 2 + 0] + dh * g_x[idx];
                g_y[idx + 1] += el * acc[mi][nj][rr * 2 + 1] + dh * g_x[idx + 1];
            }
        }
    }
}

// ================== y *= silu(z); RMSNorm * norm_w (in place) ===============
__global__ __launch_bounds__(256)
void gate_norm(const float* __restrict__ norm_w)
{
    size_t row = blockIdx.x;
    int tid = threadIdx.x;
    const float* zrow = g_zxbcdt + row * DPROJ;
    float* yrow = g_y + row * DINNER;

    float v[6];
    float ss = 0.f;
    #pragma unroll
    for (int k = 0; k < 6; k++) {
        int d = tid + k * 256;
        float y = yrow[d];
        float z = zrow[d];
        float t = y * (z / (1.f + expf(-z)));
        v[k] = t;
        ss += t * t;
    }

    __shared__ float red[8];
    for (int o = 16; o; o >>= 1) ss += __shfl_xor_sync(0xffffffffu, ss, o);
    if ((tid & 31) == 0) red[tid >> 5] = ss;
    __syncthreads();
    if (tid == 0) {
        float t = 0.f;
        #pragma unroll
        for (int i = 0; i < 8; i++) t += red[i];
        red[0] = t;
    }
    __syncthreads();
    float scale = rsqrtf(red[0] * (1.f / DINNER) + 1e-5f);

    #pragma unroll
    for (int k = 0; k < 6; k++) {
        int d = tid + k * 256;
        yrow[d] = v[k] * scale * norm_w[d];
    }
}

// ============================== launcher =====================================
extern "C" void kernel_launch(void* const* d_in, const int* in_sizes, int n_in,
                              void* d_out, int out_size)
{
    const float* feature = (const float*)d_in[0];
    const float* gate1   = (const float*)d_in[1];
    const float* in_proj = (const float*)d_in[2];
    const float* conv_w  = (const float*)d_in[3];
    const float* conv_b  = (const float*)d_in[4];
    const float* dt_bias = (const float*)d_in[5];
    const float* A_log   = (const float*)d_in[6];
    const float* Dp      = (const float*)d_in[7];
    const float* norm_w  = (const float*)d_in[8];
    const float* out_w   = (const float*)d_in[9];
    float* out = (float*)d_out;

    float *p_zx = nullptr, *p_y = nullptr;
    cudaGetSymbolAddress((void**)&p_zx, g_zxbcdt);
    cudaGetSymbolAddress((void**)&p_y,  g_y);

    const int SMEM_CB    = (32 + 128) * 132 * 4;
    const int SMEM_CHUNK = (256 + 128 * 132 + 64 * 132 + 128 * 132) * 4;   // 169984
    const int SMEM_YOFF  = (128 * 132 + 64 * 132) * 4;
    cudaFuncSetAttribute(cb_kernel,    cudaFuncAttributeMaxDynamicSharedMemorySize, SMEM_CB);
    cudaFuncSetAttribute(chunk_kernel, cudaFuncAttributeMaxDynamicSharedMemorySize, SMEM_CHUNK);
    cudaFuncSetAttribute(yoff_kernel,  cudaFuncAttributeMaxDynamicSharedMemorySize, SMEM_YOFF);

    // 1) zxbcdt = feature @ in_proj^T
    gemm_tf32<<<dim3((DPROJ + 127) / 128, MROWS / 128), 256>>>(
        feature, in_proj, p_zx, MROWS, DPROJ, DMODEL, nullptr, nullptr);

    // 2) causal conv1d + silu -> x, B, C
    conv_act<<<(B_SZ * SEQ * (DXBC / 4)) / 256, 256>>>(conv_w, conv_b);

    // 3) dt = softplus(raw + bias)
    dt_kernel<<<(MROWS * NH) / 256, 256>>>(dt_bias);

    // 4) CB = C @ B^T per (b, chunk), 4-way row split
    cb_kernel<<<dim3(NC, B_SZ, 4), 512, SMEM_CB>>>();

    // 5) per (b, chunk, head): cumsum + Y_diag + states (tensor cores)
    chunk_kernel<<<dim3(NC, NH, B_SZ), 256, SMEM_CHUNK>>>(A_log);

    // 6) inter-chunk scan (full-chip)
    scan_kernel<<<B_SZ * NH * 8, 256>>>();

    // 7) Y_off + D*x (tensor cores)
    yoff_kernel<<<dim3(NC, NH, B_SZ), 256, SMEM_YOFF>>>(Dp);

    // 8) gate + RMSNorm
    gate_norm<<<MROWS, 256>>>(norm_w);

    // 9) out = sigmoid(gate1) * (y @ out_proj^T) + feature
    gemm_tf32<<<dim3(DMODEL / 128, MROWS / 128), 256>>>(
        p_y, out_w, out, MROWS, DMODEL, DINNER, feature, gate1);
}

// round 16
// speedup vs baseline: 1.6093x; 1.6093x over previous
#include <cuda_runtime.h>
#include <cuda_bf16.h>
#include <cstdint>
#include <math.h>

#define B_SZ   2
#define SEQ    4096
#define DMODEL 768
#define DPROJ  3352
#define DINNER 1536
#define DXBC   1792
#define NH     24
#define HD     64
#define DSTATE 128
#define CH     128
#define NC     32
#define MROWS  (B_SZ*SEQ)

// ---------------- scratch (static device arrays; no runtime alloc) ----------
__device__ float g_zxbcdt[(size_t)MROWS*DPROJ];
__device__ float g_x[(size_t)MROWS*DINNER];
__device__ float g_dt[(size_t)MROWS*NH];
__device__ float g_Bm[(size_t)MROWS*DSTATE];
__device__ float g_Cm[(size_t)MROWS*DSTATE];
__device__ float g_CB[(size_t)B_SZ*NC*CH*CH];
__device__ float g_Acum[(size_t)B_SZ*NC*NH*CH];
__device__ float g_Alast[(size_t)B_SZ*NC*NH];
__device__ float g_states[(size_t)B_SZ*NC*NH*HD*DSTATE];
__device__ float g_y[(size_t)MROWS*DINNER];

// =================== tf32 / async helpers ====================================
__device__ __forceinline__ unsigned f2tf(float x) {
    unsigned r;
    asm("cvt.rna.tf32.f32 %0, %1;" : "=r"(r) : "f"(x));
    return r;
}

__device__ __forceinline__ void mma_tf32(float* d, const unsigned* a, const unsigned* b) {
    asm volatile(
        "mma.sync.aligned.m16n8k8.row.col.f32.tf32.tf32.f32 "
        "{%0,%1,%2,%3}, {%4,%5,%6,%7}, {%8,%9}, {%0,%1,%2,%3};"
        : "+f"(d[0]), "+f"(d[1]), "+f"(d[2]), "+f"(d[3])
        : "r"(a[0]), "r"(a[1]), "r"(a[2]), "r"(a[3]), "r"(b[0]), "r"(b[1]));
}

__device__ __forceinline__ void cp16(void* smem, const void* gmem) {
    unsigned sa = (unsigned)__cvta_generic_to_shared(smem);
    asm volatile("cp.async.ca.shared.global [%0], [%1], 16;" :: "r"(sa), "l"(gmem));
}

// ============ tf32 tensor-core NT GEMM: out = X(MxK) * W(NxK)^T =============
// 128x128 block tile, BK=16, 2-stage cp.async pipeline, 8 warps (4x2), 2 CTAs/SM.
__global__ __launch_bounds__(256, 2)
void gemm_tf32(const float* __restrict__ X, const float* __restrict__ W,
               float* __restrict__ out, int M, int N, int K,
               const float* __restrict__ resid, const float* __restrict__ gate)
{
    __shared__ float As[2][128][20];
    __shared__ float Bs[2][128][20];

    const int tid  = threadIdx.x;
    const int warp = tid >> 5;
    const int lane = tid & 31;
    const int gid  = lane >> 2;
    const int tig  = lane & 3;
    const int wm   = warp >> 1;
    const int wn   = warp & 1;

    const int m0 = blockIdx.y * 128;
    const int n0 = blockIdx.x * 128;

    const int lr = tid >> 2;
    const int lc = (tid & 3) * 4;

    const bool bv0 = (n0 + lr      < N);
    const bool bv1 = (n0 + lr + 64 < N);

    if (!bv0) { *(float4*)&Bs[0][lr][lc] = make_float4(0,0,0,0);
                *(float4*)&Bs[1][lr][lc] = make_float4(0,0,0,0); }
    if (!bv1) { *(float4*)&Bs[0][lr+64][lc] = make_float4(0,0,0,0);
                *(float4*)&Bs[1][lr+64][lc] = make_float4(0,0,0,0); }

    float acc[2][8][4];
    #pragma unroll
    for (int i = 0; i < 2; i++)
        #pragma unroll
        for (int j = 0; j < 8; j++)
            #pragma unroll
            for (int c = 0; c < 4; c++) acc[i][j][c] = 0.f;

    const int ktiles = K >> 4;

    const float* gA0 = X + (size_t)(m0 + lr) * K + lc;
    const float* gA1 = X + (size_t)(m0 + lr + 64) * K + lc;
    const float* gB0 = W + (size_t)(n0 + lr) * K + lc;
    const float* gB1 = W + (size_t)(n0 + lr + 64) * K + lc;

    cp16(&As[0][lr][lc],      gA0);
    cp16(&As[0][lr + 64][lc], gA1);
    if (bv0) cp16(&Bs[0][lr][lc],      gB0);
    if (bv1) cp16(&Bs[0][lr + 64][lc], gB1);
    asm volatile("cp.async.commit_group;");

    for (int kt = 0; kt < ktiles; kt++) {
        const int s = kt & 1;
        if (kt + 1 < ktiles) {
            const int ko = (kt + 1) * 16;
            cp16(&As[s ^ 1][lr][lc],      gA0 + ko);
            cp16(&As[s ^ 1][lr + 64][lc], gA1 + ko);
            if (bv0) cp16(&Bs[s ^ 1][lr][lc],      gB0 + ko);
            if (bv1) cp16(&Bs[s ^ 1][lr + 64][lc], gB1 + ko);
            asm volatile("cp.async.commit_group;");
            asm volatile("cp.async.wait_group 1;");
        } else {
            asm volatile("cp.async.wait_group 0;");
        }
        __syncthreads();

        #pragma unroll
        for (int kk = 0; kk < 16; kk += 8) {
            unsigned afr[2][4];
            #pragma unroll
            for (int mi = 0; mi < 2; mi++) {
                const int rm = wm * 32 + mi * 16;
                afr[mi][0] = f2tf(As[s][rm + gid    ][kk + tig]);
                afr[mi][1] = f2tf(As[s][rm + gid + 8][kk + tig]);
                afr[mi][2] = f2tf(As[s][rm + gid    ][kk + tig + 4]);
                afr[mi][3] = f2tf(As[s][rm + gid + 8][kk + tig + 4]);
            }
            #pragma unroll
            for (int j = 0; j < 8; j++) {
                const int nn = wn * 64 + j * 8 + gid;
                unsigned bfr[2];
                bfr[0] = f2tf(Bs[s][nn][kk + tig]);
                bfr[1] = f2tf(Bs[s][nn][kk + tig + 4]);
                mma_tf32(acc[0][j], afr[0], bfr);
                mma_tf32(acc[1][j], afr[1], bfr);
            }
        }
        __syncthreads();
    }

    float sg = 1.f;
    if (gate) sg = 1.f / (1.f + expf(-gate[0]));

    #pragma unroll
    for (int mi = 0; mi < 2; mi++) {
        #pragma unroll
        for (int j = 0; j < 8; j++) {
            const int n = n0 + wn * 64 + j * 8 + tig * 2;
            #pragma unroll
            for (int rr = 0; rr < 2; rr++) {
                const int m = m0 + wm * 32 + mi * 16 + gid + rr * 8;
                float v0 = acc[mi][j][rr * 2 + 0];
                float v1 = acc[mi][j][rr * 2 + 1];
                if (resid) {
                    if (n     < N) out[(size_t)m * N + n]     = sg * v0 + resid[(size_t)m * N + n];
                    if (n + 1 < N) out[(size_t)m * N + n + 1] = sg * v1 + resid[(size_t)m * N + n + 1];
                } else {
                    if (n     < N) out[(size_t)m * N + n]     = v0;
                    if (n + 1 < N) out[(size_t)m * N + n + 1] = v1;
                }
            }
        }
    }
}

// ====================== conv1d + SiLU (float4 over channels) ================
__global__ void conv_act(const float* __restrict__ conv_w,
                         const float* __restrict__ conv_b)
{
    int idx = blockIdx.x * blockDim.x + threadIdx.x;
    const int J4 = DXBC / 4;
    if (idx >= B_SZ * SEQ * J4) return;
    int j4 = idx % J4;
    int l  = (idx / J4) % SEQ;
    int b  = idx / (J4 * SEQ);
    int j  = j4 * 4;

    const float* base = g_zxbcdt + (size_t)b * SEQ * DPROJ + DINNER + j;
    float4 acc = make_float4(conv_b[j], conv_b[j+1], conv_b[j+2], conv_b[j+3]);
    #pragma unroll
    for (int k = 0; k < 4; k++) {
        int li = l + k - 3;
        if (li >= 0) {
            float4 v = *(const float4*)(base + (size_t)li * DPROJ);
            acc.x = fmaf(conv_w[(j+0)*4 + k], v.x, acc.x);
            acc.y = fmaf(conv_w[(j+1)*4 + k], v.y, acc.y);
            acc.z = fmaf(conv_w[(j+2)*4 + k], v.z, acc.z);
            acc.w = fmaf(conv_w[(j+3)*4 + k], v.w, acc.w);
        }
    }
    float4 v4;
    v4.x = acc.x / (1.f + expf(-acc.x));
    v4.y = acc.y / (1.f + expf(-acc.y));
    v4.z = acc.z / (1.f + expf(-acc.z));
    v4.w = acc.w / (1.f + expf(-acc.w));

    size_t row = (size_t)b * SEQ + l;
    if (j < DINNER)               *(float4*)&g_x [row * DINNER + j] = v4;
    else if (j < DINNER + DSTATE) *(float4*)&g_Bm[row * DSTATE + (j - DINNER)] = v4;
    else                          *(float4*)&g_Cm[row * DSTATE + (j - DINNER - DSTATE)] = v4;
}

// ============================ dt = softplus ==================================
__global__ void dt_kernel(const float* __restrict__ dt_bias)
{
    int idx = blockIdx.x * blockDim.x + threadIdx.x;
    if (idx >= MROWS * NH) return;
    int h = idx % NH;
    size_t row = idx / NH;
    float x = g_zxbcdt[row * DPROJ + (DPROJ - NH) + h] + dt_bias[h];
    g_dt[idx] = (x > 20.f) ? x : log1pf(expf(x));
}

// ========== CB[l][s] = sum_n C[l,n]*B[s,n], split 4-way over l ==============
__global__ __launch_bounds__(512)
void cb_kernel()
{
    int c = blockIdx.x, b = blockIdx.y, z = blockIdx.z;
    extern __shared__ float sm[];
    float* Csh = sm;               // 32*132
    float* Bsh = sm + 32 * 132;    // 128*132
    int tid = threadIdx.x;
    size_t rowbase = (size_t)b * SEQ + (size_t)c * CH;
    const int l0 = z * 32;

    for (int t = tid; t < 32 * 128; t += 512) {
        int l = t >> 7, n = t & 127;
        Csh[l * 132 + n] = g_Cm[(rowbase + l0 + l) * DSTATE + n];
    }
    for (int t = tid; t < 128 * 128; t += 512) {
        int s = t >> 7, n = t & 127;
        Bsh[s * 132 + n] = g_Bm[(rowbase + s) * DSTATE + n];
    }
    __syncthreads();

    int ty = tid >> 5, tx = tid & 31;
    float acc[2][4];
    #pragma unroll
    for (int i = 0; i < 2; i++)
        #pragma unroll
        for (int j = 0; j < 4; j++) acc[i][j] = 0.f;

    for (int n = 0; n < 128; n += 4) {
        float4 cv[2], bvv[4];
        #pragma unroll
        for (int i = 0; i < 2; i++) cv[i] = *(const float4*)&Csh[(ty * 2 + i) * 132 + n];
        #pragma unroll
        for (int j = 0; j < 4; j++) bvv[j] = *(const float4*)&Bsh[(tx * 4 + j) * 132 + n];
        #pragma unroll
        for (int i = 0; i < 2; i++)
            #pragma unroll
            for (int j = 0; j < 4; j++)
                acc[i][j] += cv[i].x * bvv[j].x + cv[i].y * bvv[j].y
                           + cv[i].z * bvv[j].z + cv[i].w * bvv[j].w;
    }

    float* outp = g_CB + ((size_t)b * NC + c) * CH * CH;
    #pragma unroll
    for (int i = 0; i < 2; i++)
        #pragma unroll
        for (int j = 0; j < 4; j++)
            outp[(l0 + ty * 2 + i) * CH + tx * 4 + j] = acc[i][j];
}

// ========== per (b,c,h): cumsum, Y_diag (MMA), states (MMA) ==================
// Epilogues staged through smem -> fully coalesced float4 global writes.
__global__ __launch_bounds__(256)
void chunk_kernel(const float* __restrict__ A_log)
{
    int c = blockIdx.x, h = blockIdx.y, b = blockIdx.z;
    extern __shared__ float sm[];
    float* Ac   = sm;                    // 128
    float* wd   = sm + 128;              // 128
    float* G    = sm + 256;              // 128*132  [l][s]; reused as staging
    float* xdsT = G + 128 * 132;         // 64*132   [p][l]
    float* BsT  = xdsT + 64 * 132;       // 128*132  [n][l]

    const int tid  = threadIdx.x;
    const int warp = tid >> 5;
    const int lane = tid & 31;
    const int gid  = lane >> 2;
    const int tig  = lane & 3;
    size_t rowbase = (size_t)b * SEQ + (size_t)c * CH;

    // ---- chunk-local inclusive cumsum of dt*A ----
    if (tid < 128) {
        float Ah  = -expf(A_log[h]);
        float dtv = g_dt[(rowbase + tid) * NH + h];
        Ac[tid] = dtv * Ah;
    }
    __syncthreads();
    for (int off = 1; off < 128; off <<= 1) {
        float add = 0.f;
        if (tid < 128 && tid >= off) add = Ac[tid - off];
        __syncthreads();
        if (tid < 128) Ac[tid] += add;
        __syncthreads();
    }
    float Alast = Ac[127];
    if (tid < 128) {
        wd[tid] = expf(Alast - Ac[tid]);
        g_Acum[(((size_t)b * NC + c) * NH + h) * CH + tid] = Ac[tid];
    }
    if (tid == 127) g_Alast[((size_t)b * NC + c) * NH + h] = Alast;

    // ---- stage xd^T [p][l], B^T [n][l], masked decay matrix G [l][s] ----
    for (int t = tid; t < 128 * 64; t += 256) {
        int l = t >> 6, p = t & 63;
        size_t row = rowbase + l;
        xdsT[p * 132 + l] = g_x[row * DINNER + h * HD + p] * g_dt[row * NH + h];
    }
    for (int t = tid; t < 128 * 128; t += 256) {
        int l = t >> 7, n = t & 127;
        BsT[n * 132 + l] = g_Bm[(rowbase + l) * DSTATE + n];
    }
    const float* CBp = g_CB + ((size_t)b * NC + c) * CH * CH;
    for (int t = tid; t < 128 * 128; t += 256) {
        int l = t >> 7, s = t & 127;
        G[l * 132 + s] = (s <= l) ? CBp[t] * expf(Ac[l] - Ac[s]) : 0.f;
    }
    __syncthreads();

    // ---- Y_diag[l,p] = sum_s G[l,s] * xd[s,p] via MMA (M=128,N=64,K=128) ----
    {
        const int wm = warp >> 1;   // 0..3
        const int wn = warp & 1;    // 0..1
        float acc[2][4][4];
        #pragma unroll
        for (int i = 0; i < 2; i++)
            #pragma unroll
            for (int j = 0; j < 4; j++)
                #pragma unroll
                for (int k = 0; k < 4; k++) acc[i][j][k] = 0.f;

        for (int kk = 0; kk < 128; kk += 8) {
            unsigned afr[2][4];
            #pragma unroll
            for (int mi = 0; mi < 2; mi++) {
                const int rm = wm * 32 + mi * 16;
                afr[mi][0] = f2tf(G[(rm + gid    ) * 132 + kk + tig]);
                afr[mi][1] = f2tf(G[(rm + gid + 8) * 132 + kk + tig]);
                afr[mi][2] = f2tf(G[(rm + gid    ) * 132 + kk + tig + 4]);
                afr[mi][3] = f2tf(G[(rm + gid + 8) * 132 + kk + tig + 4]);
            }
            #pragma unroll
            for (int nj = 0; nj < 4; nj++) {
                const int nn = wn * 32 + nj * 8 + gid;
                unsigned bfr[2];
                bfr[0] = f2tf(xdsT[nn * 132 + kk + tig]);
                bfr[1] = f2tf(xdsT[nn * 132 + kk + tig + 4]);
                mma_tf32(acc[0][nj], afr[0], bfr);
                mma_tf32(acc[1][nj], afr[1], bfr);
            }
        }
        __syncthreads();   // all warps done reading G
        // stage Y into G as [l][p] stride 68
        #pragma unroll
        for (int mi = 0; mi < 2; mi++)
            #pragma unroll
            for (int nj = 0; nj < 4; nj++) {
                const int n = wn * 32 + nj * 8 + tig * 2;
                #pragma unroll
                for (int rr = 0; rr < 2; rr++) {
                    const int m = wm * 32 + mi * 16 + gid + rr * 8;
                    G[m * 68 + n]     = acc[mi][nj][rr * 2 + 0];
                    G[m * 68 + n + 1] = acc[mi][nj][rr * 2 + 1];
                }
            }
        __syncthreads();
        // coalesced float4 write to g_y
        #pragma unroll
        for (int it = 0; it < 8; it++) {
            int t = tid + it * 256;
            int l = t >> 4, c4 = (t & 15) << 2;
            float4 v = *(float4*)&G[l * 68 + c4];
            *(float4*)&g_y[(rowbase + l) * DINNER + h * HD + c4] = v;
        }
    }

    // ---- states[p,n] = sum_l xd[l,p]*wd[l]*B[l,n] via MMA (M=64,N=128,K=128) ----
    {
        const int wm = warp >> 2;   // 0..1
        const int wn = warp & 3;    // 0..3
        float acc[2][4][4];
        #pragma unroll
        for (int i = 0; i < 2; i++)
            #pragma unroll
            for (int j = 0; j < 4; j++)
                #pragma unroll
                for (int k = 0; k < 4; k++) acc[i][j][k] = 0.f;

        for (int kk = 0; kk < 128; kk += 8) {
            const float wlo = wd[kk + tig];
            const float whi = wd[kk + tig + 4];
            unsigned afr[2][4];
            #pragma unroll
            for (int mi = 0; mi < 2; mi++) {
                const int rm = wm * 32 + mi * 16;
                afr[mi][0] = f2tf(xdsT[(rm + gid    ) * 132 + kk + tig] * wlo);
                afr[mi][1] = f2tf(xdsT[(rm + gid + 8) * 132 + kk + tig] * wlo);
                afr[mi][2] = f2tf(xdsT[(rm + gid    ) * 132 + kk + tig + 4] * whi);
                afr[mi][3] = f2tf(xdsT[(rm + gid + 8) * 132 + kk + tig + 4] * whi);
            }
            #pragma unroll
            for (int nj = 0; nj < 4; nj++) {
                const int nn = wn * 32 + nj * 8 + gid;
                unsigned bfr[2];
                bfr[0] = f2tf(BsT[nn * 132 + kk + tig]);
                bfr[1] = f2tf(BsT[nn * 132 + kk + tig + 4]);
                mma_tf32(acc[0][nj], afr[0], bfr);
                mma_tf32(acc[1][nj], afr[1], bfr);
            }
        }
        __syncthreads();   // Y-coalesced reads of G complete everywhere
        // stage states into G as [p][n] stride 132
        #pragma unroll
        for (int mi = 0; mi < 2; mi++)
            #pragma unroll
            for (int nj = 0; nj < 4; nj++) {
                const int n = wn * 32 + nj * 8 + tig * 2;
                #pragma unroll
                for (int rr = 0; rr < 2; rr++) {
                    const int m = wm * 32 + mi * 16 + gid + rr * 8;
                    G[m * 132 + n]     = acc[mi][nj][rr * 2 + 0];
                    G[m * 132 + n + 1] = acc[mi][nj][rr * 2 + 1];
                }
            }
        __syncthreads();
        float* sp = g_states + (((size_t)b * NC + c) * NH + h) * HD * DSTATE;
        #pragma unroll
        for (int it = 0; it < 8; it++) {
            int t = tid + it * 256;
            int p = t >> 5, c4 = (t & 31) << 2;
            float4 v = *(float4*)&G[p * 132 + c4];
            *(float4*)&sp[p * DSTATE + c4] = v;
        }
    }
}

// ========== inter-chunk scan (full-chip: 8 segments per (b,h)) ==============
__global__ __launch_bounds__(256)
void scan_kernel()
{
    int blk = blockIdx.x;
    int seg = blk & 7;
    int bh  = blk >> 3;
    int b = bh / NH, h = bh % NH;
    int t4 = seg * 256 + threadIdx.x;

    float4 run = make_float4(0.f, 0.f, 0.f, 0.f);
    for (int c = 0; c < NC; c++) {
        float el = expf(g_Alast[((size_t)b * NC + c) * NH + h]);
        float4* sp = (float4*)(g_states + (((size_t)b * NC + c) * NH + h) * (HD * DSTATE)) + t4;
        float4 s = *sp;
        *sp = run;
        run.x = fmaf(run.x, el, s.x);
        run.y = fmaf(run.y, el, s.y);
        run.z = fmaf(run.z, el, s.z);
        run.w = fmaf(run.w, el, s.w);
    }
}

// ==== Y_off[l,p] = e^{Acum[l]} * sum_n C[l,n]*prev[p,n] via MMA; + D*x ======
// Staged epilogue: coalesced float4 read-modify-write of g_y.
__global__ __launch_bounds__(256)
void yoff_kernel(const float* __restrict__ Dp)
{
    int c = blockIdx.x, h = blockIdx.y, b = blockIdx.z;
    extern __shared__ float sm[];
    float* Csh = sm;               // 128*132  [l][n]; reused as staging
    float* Pv  = sm + 128 * 132;   // 64*132   [p][n]
    const int tid  = threadIdx.x;
    const int warp = tid >> 5;
    const int lane = tid & 31;
    const int gid  = lane >> 2;
    const int tig  = lane & 3;
    size_t rowbase = (size_t)b * SEQ + (size_t)c * CH;

    for (int t = tid; t < 128 * 128; t += 256) {
        int l = t >> 7, n = t & 127;
        Csh[l * 132 + n] = g_Cm[(rowbase + l) * DSTATE + n];
    }
    const float* sp = g_states + (((size_t)b * NC + c) * NH + h) * HD * DSTATE;
    for (int t = tid; t < 64 * 128; t += 256) {
        int p = t >> 7, n = t & 127;
        Pv[p * 132 + n] = sp[t];
    }
    __syncthreads();

    const int wm = warp >> 1;   // 0..3
    const int wn = warp & 1;    // 0..1
    float acc[2][4][4];
    #pragma unroll
    for (int i = 0; i < 2; i++)
        #pragma unroll
        for (int j = 0; j < 4; j++)
            #pragma unroll
            for (int k = 0; k < 4; k++) acc[i][j][k] = 0.f;

    for (int kk = 0; kk < 128; kk += 8) {
        unsigned afr[2][4];
        #pragma unroll
        for (int mi = 0; mi < 2; mi++) {
            const int rm = wm * 32 + mi * 16;
            afr[mi][0] = f2tf(Csh[(rm + gid    ) * 132 + kk + tig]);
            afr[mi][1] = f2tf(Csh[(rm + gid + 8) * 132 + kk + tig]);
            afr[mi][2] = f2tf(Csh[(rm + gid    ) * 132 + kk + tig + 4]);
            afr[mi][3] = f2tf(Csh[(rm + gid + 8) * 132 + kk + tig + 4]);
        }
        #pragma unroll
        for (int nj = 0; nj < 4; nj++) {
            const int nn = wn * 32 + nj * 8 + gid;
            unsigned bfr[2];
            bfr[0] = f2tf(Pv[nn * 132 + kk + tig]);
            bfr[1] = f2tf(Pv[nn * 132 + kk + tig + 4]);
            mma_tf32(acc[0][nj], afr[0], bfr);
            mma_tf32(acc[1][nj], afr[1], bfr);
        }
    }

    __syncthreads();   // all warps done reading Csh
    // stage Y_off into Csh as [l][p] stride 68
    #pragma unroll
    for (int mi = 0; mi < 2; mi++)
        #pragma unroll
        for (int nj = 0; nj < 4; nj++) {
            const int n = wn * 32 + nj * 8 + tig * 2;
            #pragma unroll
            for (int rr = 0; rr < 2; rr++) {
                const int l = wm * 32 + mi * 16 + gid + rr * 8;
                Csh[l * 68 + n]     = acc[mi][nj][rr * 2 + 0];
                Csh[l * 68 + n + 1] = acc[mi][nj][rr * 2 + 1];
            }
        }
    __syncthreads();

    const float dh = Dp[h];
    const float* acp = g_Acum + (((size_t)b * NC + c) * NH + h) * CH;
    #pragma unroll
    for (int it = 0; it < 8; it++) {
        int t = tid + it * 256;
        int l = t >> 4, c4 = (t & 15) << 2;
        float el = expf(acp[l]);
        size_t idx = (rowbase + l) * DINNER + h * HD + c4;
        float4 st = *(float4*)&Csh[l * 68 + c4];
        float4 yv = *(float4*)&g_y[idx];
        float4 xv = *(float4*)&g_x[idx];
        yv.x += el * st.x + dh * xv.x;
        yv.y += el * st.y + dh * xv.y;
        yv.z += el * st.z + dh * xv.z;
        yv.w += el * st.w + dh * xv.w;
        *(float4*)&g_y[idx] = yv;
    }
}

// ================== y *= silu(z); RMSNorm * norm_w (in place) ===============
__global__ __launch_bounds__(256)
void gate_norm(const float* __restrict__ norm_w)
{
    size_t row = blockIdx.x;
    int tid = threadIdx.x;
    const float* zrow = g_zxbcdt + row * DPROJ;
    float* yrow = g_y + row * DINNER;

    float v[6];
    float ss = 0.f;
    #pragma unroll
    for (int k = 0; k < 6; k++) {
        int d = tid + k * 256;
        float y = yrow[d];
        float z = zrow[d];
        float t = y * (z / (1.f + expf(-z)));
        v[k] = t;
        ss += t * t;
    }

    __shared__ float red[8];
    for (int o = 16; o; o >>= 1) ss += __shfl_xor_sync(0xffffffffu, ss, o);
    if ((tid & 31) == 0) red[tid >> 5] = ss;
    __syncthreads();
    if (tid == 0) {
        float t = 0.f;
        #pragma unroll
        for (int i = 0; i < 8; i++) t += red[i];
        red[0] = t;
    }
    __syncthreads();
    float scale = rsqrtf(red[0] * (1.f / DINNER) + 1e-5f);

    #pragma unroll
    for (int k = 0; k < 6; k++) {
        int d = tid + k * 256;
        yrow[d] = v[k] * scale * norm_w[d];
    }
}

// ============================== launcher =====================================
extern "C" void kernel_launch(void* const* d_in, const int* in_sizes, int n_in,
                              void* d_out, int out_size)
{
    const float* feature = (const float*)d_in[0];
    const float* gate1   = (const float*)d_in[1];
    const float* in_proj = (const float*)d_in[2];
    const float* conv_w  = (const float*)d_in[3];
    const float* conv_b  = (const float*)d_in[4];
    const float* dt_bias = (const float*)d_in[5];
    const float* A_log   = (const float*)d_in[6];
    const float* Dp      = (const float*)d_in[7];
    const float* norm_w  = (const float*)d_in[8];
    const float* out_w   = (const float*)d_in[9];
    float* out = (float*)d_out;

    float *p_zx = nullptr, *p_y = nullptr;
    cudaGetSymbolAddress((void**)&p_zx, g_zxbcdt);
    cudaGetSymbolAddress((void**)&p_y,  g_y);

    const int SMEM_CB    = (32 + 128) * 132 * 4;
    const int SMEM_CHUNK = (256 + 128 * 132 + 64 * 132 + 128 * 132) * 4;
    const int SMEM_YOFF  = (128 * 132 + 64 * 132) * 4;
    cudaFuncSetAttribute(cb_kernel,    cudaFuncAttributeMaxDynamicSharedMemorySize, SMEM_CB);
    cudaFuncSetAttribute(chunk_kernel, cudaFuncAttributeMaxDynamicSharedMemorySize, SMEM_CHUNK);
    cudaFuncSetAttribute(yoff_kernel,  cudaFuncAttributeMaxDynamicSharedMemorySize, SMEM_YOFF);

    // 1) zxbcdt = feature @ in_proj^T
    gemm_tf32<<<dim3((DPROJ + 127) / 128, MROWS / 128), 256>>>(
        feature, in_proj, p_zx, MROWS, DPROJ, DMODEL, nullptr, nullptr);

    // 2) causal conv1d + silu -> x, B, C
    conv_act<<<(B_SZ * SEQ * (DXBC / 4)) / 256, 256>>>(conv_w, conv_b);

    // 3) dt = softplus(raw + bias)
    dt_kernel<<<(MROWS * NH) / 256, 256>>>(dt_bias);

    // 4) CB = C @ B^T per (b, chunk), 4-way row split
    cb_kernel<<<dim3(NC, B_SZ, 4), 512, SMEM_CB>>>();

    // 5) per (b, chunk, head): cumsum + Y_diag + states (MMA, staged epilogues)
    chunk_kernel<<<dim3(NC, NH, B_SZ), 256, SMEM_CHUNK>>>(A_log);

    // 6) inter-chunk scan (full-chip)
    scan_kernel<<<B_SZ * NH * 8, 256>>>();

    // 7) Y_off + D*x (MMA, staged epilogue)
    yoff_kernel<<<dim3(NC, NH, B_SZ), 256, SMEM_YOFF>>>(Dp);

    // 8) gate + RMSNorm
    gate_norm<<<MROWS, 256>>>(norm_w);

    // 9) out = sigmoid(gate1) * (y @ out_proj^T) + feature
    gemm_tf32<<<dim3(DMODEL / 128, MROWS / 128), 256>>>(
        p_y, out_w, out, MROWS, DMODEL, DINNER, feature, gate1);
}